// round 14
// baseline (speedup 1.0000x reference)
#include <cuda_runtime.h>
#include <cuda_fp16.h>

typedef unsigned long long ull;

// Problem constants
constexpr int H   = 75;
constexpr int H3  = 225;
constexpr int H4  = 300;
constexpr int D2  = 150;
constexpr int NB  = 256;
constexpr int LQ  = 64;
constexpr int LP  = 500;

constexpr int G    = 4;
constexpr int NTH  = 1024;            // 32 warps: latency hiding for streamed GEMVs
constexpr int NBLK = (2 * NB) / G;    // 128 blocks

constexpr int KB8 = 38;               // Wg/Wih fp16 k-blocks (300->304)
constexpr int KBG = 19;               // WPu k-blocks (150->152)
constexpr int KBH = 10;               // Whh/WPv k-blocks (75->80)
constexpr int QPS = 76;

// Shared-memory layout (float-slot offsets)
constexpr int HP   = 76;
constexpr int CCS  = 308;             // [p 0..149 | c 150..299 | pad 300..307]
constexpr int GIS  = 227;

constexpr int OFF_QPH  = 0;                      // [G][LQ][76] halves = 9728 slots
constexpr int OFF_WHH  = 9728;                   // [10][225][8] halves = 9000
constexpr int OFF_WPV  = OFF_WHH + 9000;         // [10][75][8]  = 3000
constexpr int OFF_WPU  = OFF_WPV + 3000;         // [19][75][8]  = 5700
constexpr int OFF_H    = OFF_WPU + 5700;         // [G][76]
constexpr int OFF_V    = OFF_H + G * HP;
constexpr int OFF_E    = OFF_V + G * HP;
constexpr int OFF_S    = OFF_E + G * HP;         // [G][64]
constexpr int OFF_PART = OFF_S + G * LQ;         // [2][G][64]
constexpr int OFF_CC   = OFF_PART + 2 * G * LQ;  // [G][308]
constexpr int OFF_X    = OFF_CC + G * CCS;       // [G][308]
constexpr int OFF_GI   = OFF_X + G * CCS;        // [G][227]
constexpr int OFF_GH   = OFF_GI + G * GIS;       // [G][227]
constexpr int SMEM_FLOATS = OFF_GH + G * GIS;    // 33388 slots
constexpr int SMEM_BYTES  = SMEM_FLOATS * 4;     // 133552 B -> L1 ~94KB

static_assert((OFF_WHH * 4) % 16 == 0 && (OFF_WPV * 4) % 16 == 0, "align");
static_assert((OFF_WPU * 4) % 16 == 0 && (OFF_H * 4) % 16 == 0, "align");
static_assert((OFF_CC * 4) % 16 == 0 && (OFF_X * 4) % 16 == 0, "align");
static_assert(SMEM_BYTES <= 232448, "smem over limit");

// Device scratch
__device__ __half g_QprojH[LQ * NB * H];
__device__ float  g_WQuT[D2 * H];
__device__ __align__(16) __half g_Wg4h[KB8 * H4 * 8];       // full Wg fp16 [kb][j][8]
__device__ __align__(16) __half g_Wih4h[2][KB8 * H3 * 8];   // Wih fp16 per dir

// ---------- math helpers ----------
__device__ __forceinline__ float tanha(float x) {
    float r; asm("tanh.approx.f32 %0, %1;" : "=f"(r) : "f"(x)); return r;
}
__device__ __forceinline__ float siga(float x) {
    return fmaf(tanha(0.5f * x), 0.5f, 0.5f);
}
__device__ __forceinline__ ull pack2(float x, float y) {
    ull r; asm("mov.b64 %0, {%1, %2};" : "=l"(r) : "f"(x), "f"(y)); return r;
}
__device__ __forceinline__ void fma2(ull& d, ull a, ull b) {
    asm("fma.rn.f32x2 %0, %1, %2, %0;" : "+l"(d) : "l"(a), "l"(b));
}
__device__ __forceinline__ float hsum2(ull a) {
    float x, y; asm("mov.b64 {%0, %1}, %2;" : "=f"(x), "=f"(y) : "l"(a));
    return x + y;
}
__device__ __forceinline__ ull h2f2(unsigned v) {
    float2 f = __half22float2(*reinterpret_cast<const __half2*>(&v));
    return pack2(f.x, f.y);
}

#define LD2(p, idx) (*reinterpret_cast<const ulonglong2*>((p) + (idx)))

// ---------- prep: full Wg + Wih fp16 packs ----------
__global__ void prep_kernel(const float* __restrict__ WQu,
                            const float* __restrict__ Wg,
                            const float* __restrict__ Wf,
                            const float* __restrict__ Wr) {
    int o = blockIdx.x * blockDim.x + threadIdx.x;
    if (o < D2 * H) {
        int k = o / H, j = o - k * H;
        g_WQuT[o] = WQu[j * D2 + k];
    } else if (o < D2 * H + KB8 * H4 * 8) {
        int o2 = o - D2 * H;
        int kb = o2 / 2400, r = o2 % 2400, j = r >> 3, c = r & 7;
        int k = kb * 8 + c;
        g_Wg4h[o2] = __float2half(k < H4 ? Wg[j * H4 + k] : 0.0f);
    } else if (o < D2 * H + KB8 * H4 * 8 + 2 * KB8 * H3 * 8) {
        int o2 = o - D2 * H - KB8 * H4 * 8;
        int d = o2 / (KB8 * H3 * 8);
        int o3 = o2 - d * (KB8 * H3 * 8);
        int kb = o3 / 1800, r = o3 % 1800, j = r >> 3, c = r & 7;
        int k = kb * 8 + c;
        const float* W = d ? Wr : Wf;
        g_Wih4h[d][o3] = __float2half(k < H4 ? W[j * H4 + k] : 0.0f);
    }
}
constexpr int PREP_N = D2 * H + KB8 * H4 * 8 + 2 * KB8 * H3 * 8;

// ---------- Qproj ----------
__global__ void qproj_kernel(const float* __restrict__ X,
                             const float* __restrict__ bias) {
    int o = blockIdx.x * blockDim.x + threadIdx.x;
    if (o >= LQ * NB * H) return;
    int m = o / H;
    int j = o - m * H;
    const float* xr = X + (size_t)m * D2;
    float acc = bias[j];
#pragma unroll 15
    for (int k = 0; k < D2; k++) acc = fmaf(xr[k], g_WQuT[k * H + j], acc);
    g_QprojH[o] = __float2half(acc);
}

// ---------- persistent kernel ----------
__global__ __launch_bounds__(NTH, 1)
void persist_kernel(const float* __restrict__ quesEnc,
                    const float* __restrict__ passEnc,
                    const float* __restrict__ WPu_w, const float* __restrict__ WPu_b,
                    const float* __restrict__ WPv_w, const float* __restrict__ WPv_b,
                    const float* __restrict__ Wg_b,
                    const float* __restrict__ Vt,
                    const float* __restrict__ Whh_f,
                    const float* __restrict__ bih_f, const float* __restrict__ bhh_f,
                    const float* __restrict__ Whh_r,
                    const float* __restrict__ bih_r, const float* __restrict__ bhh_r,
                    const float* __restrict__ h0f,   const float* __restrict__ h0r,
                    float* __restrict__ out) {
    extern __shared__ float sm[];
    __half* qph  = reinterpret_cast<__half*>(sm + OFF_QPH);
    __half* whhH = reinterpret_cast<__half*>(sm + OFF_WHH);
    __half* wpvH = reinterpret_cast<__half*>(sm + OFF_WPV);
    __half* wpuH = reinterpret_cast<__half*>(sm + OFF_WPU);
    const int tid   = threadIdx.x;
    const int item0 = blockIdx.x * G;
    const int dir   = item0 >> 8;

    // ---- one-time smem fills ----
    {
        const float* Whh = dir ? Whh_r : Whh_f;
        for (int idx = tid; idx < KBH * H3 * 8; idx += NTH) {
            int kb = idx / 1800, r = idx % 1800, rr = r >> 3, c = r & 7;
            int k = kb * 8 + c;
            whhH[idx] = __float2half(k < H ? Whh[rr * H + k] : 0.0f);
        }
        for (int idx = tid; idx < KBH * H * 8; idx += NTH) {
            int kb = idx / 600, r = idx % 600, j = r >> 3, c = r & 7;
            int k = kb * 8 + c;
            wpvH[idx] = __float2half(k < H ? WPv_w[j * H + k] : 0.0f);
        }
        for (int idx = tid; idx < KBG * H * 8; idx += NTH) {
            int kb = idx / 600, r = idx % 600, j = r >> 3, c = r & 7;
            int k = kb * 8 + c;
            wpuH[idx] = __float2half(k < D2 ? WPu_w[j * D2 + k] : 0.0f);
        }
        const float* h0 = dir ? h0r : h0f;
        for (int idx = tid; idx < G * HP; idx += NTH) {
            int i = idx / HP, j = idx % HP;
            int b = (item0 + i) & 255;
            sm[OFF_H + idx] = (j < H) ? h0[b * H + j] : 0.0f;
            sm[OFF_V + idx] = (j < H) ? Vt[b * H + j] : 0.0f;
            sm[OFF_E + idx] = 0.0f;
        }
        for (int idx = tid; idx < 2 * G * CCS; idx += NTH)   // zero CC + X (pads!)
            sm[OFF_CC + idx] = 0.0f;
        for (int idx = tid; idx < G * LQ * QPS; idx += NTH) {
            int i = idx / (LQ * QPS);
            int r = idx - i * (LQ * QPS);
            int q = r / QPS, j = r - q * QPS;
            int b = (item0 + i) & 255;
            qph[idx] = (j < H) ? g_QprojH[((size_t)q * NB + b) * H + j]
                               : __float2half(0.0f);
        }
        int te0 = dir ? (LP - 1) : 0;
        for (int idx = tid; idx < G * D2; idx += NTH) {      // p(0)
            int i = idx / D2, d = idx - i * D2;
            int b = (item0 + i) & 255;
            sm[OFF_CC + i * CCS + d] = passEnc[((size_t)te0 * NB + b) * D2 + d];
        }
    }

    // ---- hoisted constants ----
    const unsigned pm = 3u << (tid & 30);                // pair shfl mask
    const unsigned qm = 0xFu << (tid & 28);              // quad shfl mask

    // p1-e: tid<600: row r1=tid>>1, kh1: 0->WPu(19kb), 1->WPv(10kb)
    const int r1 = (tid >> 1) % 300, kh1 = tid & 1;
    const int i1e = r1 / H, j1e = r1 % H;
    const float b_ph1 = (WPu_b[j1e] + WPv_b[j1e]);

    // p1-gh: tid>=600: pair rows rp stride 212
    const int ghp0 = (tid - 600) >> 1;                   // valid when tid>=600
    const float* bhh_d = dir ? bhh_r : bhh_f;

    // p2 score: tid<512: half/pr/i2/q2
    const int half = tid & 1, pr = (tid >> 1) & 255;
    const int i2 = pr >> 6, q2 = pr & 63;
    const __half2* qp2 = reinterpret_cast<const __half2*>(qph + i2 * (LQ * QPS) + q2 * QPS)
                         + (half ? 19 : 0);
    const float2* ee2 = reinterpret_cast<const float2*>(sm + OFF_E + i2 * HP) + (half ? 19 : 0);
    const float2* vv2 = reinterpret_cast<const float2*>(sm + OFF_V + i2 * HP) + (half ? 19 : 0);

    // p4: tid<600: pd = tid>>1, qh
    const int pd = (tid >> 1) % 300, qh = tid & 1;
    const int i4 = pd / 75, d4 = pd % 75;

    // p5: tid<600: row j5=tid>>1, kh5 -> kb range
    const int j5 = (tid >> 1) % 300, kh5 = tid & 1;
    const int i5g = j5 / 75;   (void)i5g;
    const float b_g5 = Wg_b[j5];

    // p6: tid<900: j6=tid>>2, ks
    const int j6 = (tid >> 2) % 225, ks = tid & 3;
    const int kb6lo = (ks == 0) ? 0 : (ks == 1) ? 10 : (ks == 2) ? 20 : 29;
    const int kb6n  = (ks < 2) ? 10 : 9;
    const float b_ih6 = (dir ? bih_r : bih_f)[j6];

    // p7: tid<300
    const int i7 = tid / H, j7 = tid % H;

    const uint4* wg_all = reinterpret_cast<const uint4*>(g_Wg4h);
    const uint4* wi_all = reinterpret_cast<const uint4*>(g_Wih4h[dir]);
    const uint4* whh_u4 = reinterpret_cast<const uint4*>(whhH);
    const uint4* wpv_u4 = reinterpret_cast<const uint4*>(wpvH);
    const uint4* wpu_u4 = reinterpret_cast<const uint4*>(wpuH);

    const ull* x0c = reinterpret_cast<const ull*>(sm + OFF_CC);
    const ull* x1c = reinterpret_cast<const ull*>(sm + OFF_CC + CCS);
    const ull* x2c = reinterpret_cast<const ull*>(sm + OFF_CC + 2 * CCS);
    const ull* x3c = reinterpret_cast<const ull*>(sm + OFF_CC + 3 * CCS);
    const ull* x0x = reinterpret_cast<const ull*>(sm + OFF_X);
    const ull* x1x = reinterpret_cast<const ull*>(sm + OFF_X + CCS);
    const ull* x2x = reinterpret_cast<const ull*>(sm + OFF_X + 2 * CCS);
    const ull* x3x = reinterpret_cast<const ull*>(sm + OFF_X + 3 * CCS);
    const ull* hh0 = reinterpret_cast<const ull*>(sm + OFF_H);
    const ull* hh1 = reinterpret_cast<const ull*>(sm + OFF_H + HP);
    const ull* hh2 = reinterpret_cast<const ull*>(sm + OFF_H + 2 * HP);
    const ull* hh3 = reinterpret_cast<const ull*>(sm + OFF_H + 3 * HP);

    __syncthreads();

    // ================= main 500-step loop =================
    for (int t = 0; t < LP; t++) {
        float pf0 = 0.0f, pf1 = 0.0f, pf2 = 0.0f;

        // ---- phase 1: e-GEMV pair-split (tid<600) || gh pair-split (tid>=600) ----
        if (tid < 600) {
            ull aA = 0ull, aB = 0ull;
            const ull* pp = (i1e == 0) ? x0c : (i1e == 1) ? x1c : (i1e == 2) ? x2c : x3c;
            const ull* hh = (i1e == 0) ? hh0 : (i1e == 1) ? hh1 : (i1e == 2) ? hh2 : hh3;
            if (kh1 == 0) {
#pragma unroll
                for (int kb = 0; kb < KBG; kb++) {           // WPu @ p
                    uint4 w = wpu_u4[kb * H + j1e];
                    ull w0 = h2f2(w.x), w1 = h2f2(w.y), w2 = h2f2(w.z), w3 = h2f2(w.w);
                    ulonglong2 pa = LD2(pp, 4 * kb), pb = LD2(pp, 4 * kb + 2);
                    fma2(aA, w0, pa.x); fma2(aB, w1, pa.y);
                    fma2(aA, w2, pb.x); fma2(aB, w3, pb.y);
                }
            } else {
#pragma unroll
                for (int kb = 0; kb < KBH; kb++) {           // WPv @ h
                    uint4 w = wpv_u4[kb * H + j1e];
                    ull w0 = h2f2(w.x), w1 = h2f2(w.y), w2 = h2f2(w.z), w3 = h2f2(w.w);
                    ulonglong2 pa = LD2(hh, 4 * kb), pb = LD2(hh, 4 * kb + 2);
                    fma2(aA, w0, pa.x); fma2(aB, w1, pa.y);
                    fma2(aA, w2, pb.x); fma2(aB, w3, pb.y);
                }
            }
            float part = hsum2(aA) + hsum2(aB);
            part += __shfl_xor_sync(pm, part, 1);
            if (kh1 == 0) sm[OFF_E + i1e * HP + j1e] = part + b_ph1;
        } else {
            const int khg = tid & 1;
            const int kbg0 = khg * 5;                        // 5 kb each half
            for (int rp = ghp0; rp < H3; rp += 212) {
                ull a0A = 0, a0B = 0, a1A = 0, a1B = 0;
                ull a2A = 0, a2B = 0, a3A = 0, a3B = 0;
#pragma unroll
                for (int kk = 0; kk < 5; kk++) {
                    int kb = kbg0 + kk;
                    uint4 w = whh_u4[kb * H3 + rp];
                    ull w0 = h2f2(w.x), w1 = h2f2(w.y), w2 = h2f2(w.z), w3 = h2f2(w.w);
                    ulonglong2 pa, pb;
                    pa = LD2(hh0, 4 * kb); pb = LD2(hh0, 4 * kb + 2);
                    fma2(a0A, w0, pa.x); fma2(a0B, w1, pa.y); fma2(a0A, w2, pb.x); fma2(a0B, w3, pb.y);
                    pa = LD2(hh1, 4 * kb); pb = LD2(hh1, 4 * kb + 2);
                    fma2(a1A, w0, pa.x); fma2(a1B, w1, pa.y); fma2(a1A, w2, pb.x); fma2(a1B, w3, pb.y);
                    pa = LD2(hh2, 4 * kb); pb = LD2(hh2, 4 * kb + 2);
                    fma2(a2A, w0, pa.x); fma2(a2B, w1, pa.y); fma2(a2A, w2, pb.x); fma2(a2B, w3, pb.y);
                    pa = LD2(hh3, 4 * kb); pb = LD2(hh3, 4 * kb + 2);
                    fma2(a3A, w0, pa.x); fma2(a3B, w1, pa.y); fma2(a3A, w2, pb.x); fma2(a3B, w3, pb.y);
                }
                float g0 = hsum2(a0A) + hsum2(a0B);
                float g1 = hsum2(a1A) + hsum2(a1B);
                float g2 = hsum2(a2A) + hsum2(a2B);
                float g3 = hsum2(a3A) + hsum2(a3B);
                g0 += __shfl_xor_sync(pm, g0, 1);
                g1 += __shfl_xor_sync(pm, g1, 1);
                g2 += __shfl_xor_sync(pm, g2, 1);
                g3 += __shfl_xor_sync(pm, g3, 1);
                if (khg == 0) {
                    float bb = bhh_d[rp];
                    sm[OFF_GH + 0 * GIS + rp] = g0 + bb;
                    sm[OFF_GH + 1 * GIS + rp] = g1 + bb;
                    sm[OFF_GH + 2 * GIS + rp] = g2 + bb;
                    sm[OFF_GH + 3 * GIS + rp] = g3 + bb;
                }
            }
        }
        __syncthreads();

        // ---- phase 2: scores j-split (tid<512) || passEnc prefetch (512..711) ----
        if (tid < 512) {
            float acc = 0.0f;
#pragma unroll
            for (int u = 0; u < 19; u++) {
                float2 qp = __half22float2(qp2[u]);
                float2 e = ee2[u], v = vv2[u];
                acc = fmaf(tanha(qp.x + e.x), v.x, acc);
                acc = fmaf(tanha(qp.y + e.y), v.y, acc);
            }
            sm[OFF_PART + half * (G * LQ) + i2 * LQ + q2] = acc;
        } else if (tid < 712) {
            int u = tid - 512;
            int tn = (t + 1 < LP) ? t + 1 : t;
            int ten = dir ? (LP - 1 - tn) : tn;
#pragma unroll
            for (int c = 0; c < 3; c++) {
                int e = 3 * u + c;
                int i = e / D2, d = e - i * D2;
                int b = (item0 + i) & 255;
                float v = passEnc[((size_t)ten * NB + b) * D2 + d];
                if (c == 0) pf0 = v; else if (c == 1) pf1 = v; else pf2 = v;
            }
        }
        __syncthreads();

        // ---- phase 3: softmax (warps 0..3) ----
        {
            int wid = tid >> 5, lane = tid & 31;
            if (wid < G) {
                float v0 = sm[OFF_PART + wid * LQ + lane]      + sm[OFF_PART + G * LQ + wid * LQ + lane];
                float v1 = sm[OFF_PART + wid * LQ + lane + 32] + sm[OFF_PART + G * LQ + wid * LQ + lane + 32];
                float m = fmaxf(v0, v1);
#pragma unroll
                for (int o = 16; o > 0; o >>= 1) m = fmaxf(m, __shfl_xor_sync(0xffffffffu, m, o));
                float e0 = __expf(v0 - m), e1 = __expf(v1 - m);
                float s = e0 + e1;
#pragma unroll
                for (int o = 16; o > 0; o >>= 1) s += __shfl_xor_sync(0xffffffffu, s, o);
                float inv = __fdividef(1.0f, s);
                sm[OFF_S + wid * LQ + lane]      = e0 * inv;
                sm[OFF_S + wid * LQ + lane + 32] = e1 * inv;
            }
        }
        __syncthreads();

        // ---- phase 4: context pair-split q (tid<600) ----
        if (tid < 600) {
            int b = (item0 + i4) & 255;
            const float2* qe2 = reinterpret_cast<const float2*>(quesEnc + (size_t)b * D2)
                                + d4 + (size_t)(qh * 32) * (NB * 75);
            const float4* a4 = reinterpret_cast<const float4*>(sm + OFF_S + i4 * LQ) + qh * 8;
            float ax = 0.0f, ay = 0.0f;
#pragma unroll
            for (int q4 = 0; q4 < 8; q4++) {
                float4 av = a4[q4];
                float2 v0 = qe2[(4 * q4 + 0) * (NB * 75)];
                float2 v1 = qe2[(4 * q4 + 1) * (NB * 75)];
                float2 v2 = qe2[(4 * q4 + 2) * (NB * 75)];
                float2 v3 = qe2[(4 * q4 + 3) * (NB * 75)];
                ax = fmaf(av.x, v0.x, ax); ay = fmaf(av.x, v0.y, ay);
                ax = fmaf(av.y, v1.x, ax); ay = fmaf(av.y, v1.y, ay);
                ax = fmaf(av.z, v2.x, ax); ay = fmaf(av.z, v2.y, ay);
                ax = fmaf(av.w, v3.x, ax); ay = fmaf(av.w, v3.y, ay);
            }
            ax += __shfl_xor_sync(pm, ax, 1);
            ay += __shfl_xor_sync(pm, ay, 1);
            if (qh == 0)
                reinterpret_cast<float2*>(sm + OFF_CC + i4 * CCS)[75 + d4] = make_float2(ax, ay);
        }
        __syncthreads();

        // ---- phase 5: Wg GEMV pair-split k (tid<600), fp16 global stream ----
        if (tid < 600) {
            ull a0A = 0, a0B = 0, a1A = 0, a1B = 0;
            ull a2A = 0, a2B = 0, a3A = 0, a3B = 0;
            const int kb0 = kh5 * 19;
#pragma unroll 19
            for (int kk = 0; kk < 19; kk++) {
                int kb = kb0 + kk;
                uint4 w = wg_all[kb * H4 + j5];
                ull w0 = h2f2(w.x), w1 = h2f2(w.y), w2 = h2f2(w.z), w3 = h2f2(w.w);
                ulonglong2 pa, pb;
                pa = LD2(x0c, 4 * kb); pb = LD2(x0c, 4 * kb + 2);
                fma2(a0A, w0, pa.x); fma2(a0B, w1, pa.y); fma2(a0A, w2, pb.x); fma2(a0B, w3, pb.y);
                pa = LD2(x1c, 4 * kb); pb = LD2(x1c, 4 * kb + 2);
                fma2(a1A, w0, pa.x); fma2(a1B, w1, pa.y); fma2(a1A, w2, pb.x); fma2(a1B, w3, pb.y);
                pa = LD2(x2c, 4 * kb); pb = LD2(x2c, 4 * kb + 2);
                fma2(a2A, w0, pa.x); fma2(a2B, w1, pa.y); fma2(a2A, w2, pb.x); fma2(a2B, w3, pb.y);
                pa = LD2(x3c, 4 * kb); pb = LD2(x3c, 4 * kb + 2);
                fma2(a3A, w0, pa.x); fma2(a3B, w1, pa.y); fma2(a3A, w2, pb.x); fma2(a3B, w3, pb.y);
            }
            float g0 = hsum2(a0A) + hsum2(a0B);
            float g1 = hsum2(a1A) + hsum2(a1B);
            float g2 = hsum2(a2A) + hsum2(a2B);
            float g3 = hsum2(a3A) + hsum2(a3B);
            g0 += __shfl_xor_sync(pm, g0, 1);
            g1 += __shfl_xor_sync(pm, g1, 1);
            g2 += __shfl_xor_sync(pm, g2, 1);
            g3 += __shfl_xor_sync(pm, g3, 1);
            if (kh5 == 0) {
                sm[OFF_X + 0 * CCS + j5] = siga(g0 + b_g5) * sm[OFF_CC + 0 * CCS + j5];
                sm[OFF_X + 1 * CCS + j5] = siga(g1 + b_g5) * sm[OFF_CC + 1 * CCS + j5];
                sm[OFF_X + 2 * CCS + j5] = siga(g2 + b_g5) * sm[OFF_CC + 2 * CCS + j5];
                sm[OFF_X + 3 * CCS + j5] = siga(g3 + b_g5) * sm[OFF_CC + 3 * CCS + j5];
            }
        }
        __syncthreads();

        // ---- phase 6: Wih GEMV 4-way split k (tid<900), fp16 global stream ----
        if (tid < 900) {
            ull a0A = 0, a0B = 0, a1A = 0, a1B = 0;
            ull a2A = 0, a2B = 0, a3A = 0, a3B = 0;
            for (int kk = 0; kk < kb6n; kk++) {
                int kb = kb6lo + kk;
                uint4 w = wi_all[kb * H3 + j6];
                ull w0 = h2f2(w.x), w1 = h2f2(w.y), w2 = h2f2(w.z), w3 = h2f2(w.w);
                ulonglong2 pa, pb;
                pa = LD2(x0x, 4 * kb); pb = LD2(x0x, 4 * kb + 2);
                fma2(a0A, w0, pa.x); fma2(a0B, w1, pa.y); fma2(a0A, w2, pb.x); fma2(a0B, w3, pb.y);
                pa = LD2(x1x, 4 * kb); pb = LD2(x1x, 4 * kb + 2);
                fma2(a1A, w0, pa.x); fma2(a1B, w1, pa.y); fma2(a1A, w2, pb.x); fma2(a1B, w3, pb.y);
                pa = LD2(x2x, 4 * kb); pb = LD2(x2x, 4 * kb + 2);
                fma2(a2A, w0, pa.x); fma2(a2B, w1, pa.y); fma2(a2A, w2, pb.x); fma2(a2B, w3, pb.y);
                pa = LD2(x3x, 4 * kb); pb = LD2(x3x, 4 * kb + 2);
                fma2(a3A, w0, pa.x); fma2(a3B, w1, pa.y); fma2(a3A, w2, pb.x); fma2(a3B, w3, pb.y);
            }
            float g0 = hsum2(a0A) + hsum2(a0B);
            float g1 = hsum2(a1A) + hsum2(a1B);
            float g2 = hsum2(a2A) + hsum2(a2B);
            float g3 = hsum2(a3A) + hsum2(a3B);
            g0 += __shfl_xor_sync(qm, g0, 1); g0 += __shfl_xor_sync(qm, g0, 2);
            g1 += __shfl_xor_sync(qm, g1, 1); g1 += __shfl_xor_sync(qm, g1, 2);
            g2 += __shfl_xor_sync(qm, g2, 1); g2 += __shfl_xor_sync(qm, g2, 2);
            g3 += __shfl_xor_sync(qm, g3, 1); g3 += __shfl_xor_sync(qm, g3, 2);
            if (ks == 0) {
                sm[OFF_GI + 0 * GIS + j6] = g0 + b_ih6;
                sm[OFF_GI + 1 * GIS + j6] = g1 + b_ih6;
                sm[OFF_GI + 2 * GIS + j6] = g2 + b_ih6;
                sm[OFF_GI + 3 * GIS + j6] = g3 + b_ih6;
            }
        }
        __syncthreads();

        // ---- phase 7: GRU combine + out (tid<300) || store p(t+1) (512..711) ----
        if (tid < G * H) {
            int i = i7, j = j7;
            float gr  = sm[OFF_GI + i * GIS + j]         + sm[OFF_GH + i * GIS + j];
            float gz  = sm[OFF_GI + i * GIS + H + j]     + sm[OFF_GH + i * GIS + H + j];
            float gin = sm[OFF_GI + i * GIS + 2 * H + j];
            float ghn = sm[OFF_GH + i * GIS + 2 * H + j];
            float r = siga(gr);
            float z = siga(gz);
            float n = tanha(fmaf(r, ghn, gin));
            float hn = (1.0f - z) * n + z * sm[OFF_H + i * HP + j];
            sm[OFF_H + i * HP + j] = hn;
            int b = (item0 + i) & 255;
            out[((size_t)t * NB + b) * D2 + dir * H + j] = hn;
        } else if (tid >= 512 && tid < 712) {
            int u = tid - 512;
#pragma unroll
            for (int c = 0; c < 3; c++) {
                int e = 3 * u + c;
                int i = e / D2, d = e - i * D2;
                float v = (c == 0) ? pf0 : (c == 1) ? pf1 : pf2;
                sm[OFF_CC + i * CCS + d] = v;
            }
        }
        __syncthreads();
    }
}

extern "C" void kernel_launch(void* const* d_in, const int* in_sizes, int n_in,
                              void* d_out, int out_size) {
    const float* quesEnc = (const float*)d_in[0];
    const float* passEnc = (const float*)d_in[1];
    const float* WQu_w   = (const float*)d_in[2];
    const float* WQu_b   = (const float*)d_in[3];
    const float* WPu_w   = (const float*)d_in[4];
    const float* WPu_b   = (const float*)d_in[5];
    const float* WPv_w   = (const float*)d_in[6];
    const float* WPv_b   = (const float*)d_in[7];
    const float* Wg_w    = (const float*)d_in[8];
    const float* Wg_b    = (const float*)d_in[9];
    const float* Vt      = (const float*)d_in[10];
    const float* Wih_f   = (const float*)d_in[11];
    const float* Whh_f   = (const float*)d_in[12];
    const float* bih_f   = (const float*)d_in[13];
    const float* bhh_f   = (const float*)d_in[14];
    const float* Wih_r   = (const float*)d_in[15];
    const float* Whh_r   = (const float*)d_in[16];
    const float* bih_r   = (const float*)d_in[17];
    const float* bhh_r   = (const float*)d_in[18];
    const float* h0f     = (const float*)d_in[19];
    const float* h0r     = (const float*)d_in[20];
    float* out = (float*)d_out;

    cudaFuncSetAttribute(persist_kernel,
                         cudaFuncAttributeMaxDynamicSharedMemorySize, SMEM_BYTES);

    prep_kernel<<<(PREP_N + 255) / 256, 256>>>(WQu_w, Wg_w, Wih_f, Wih_r);
    qproj_kernel<<<(LQ * NB * H + 255) / 256, 256>>>(quesEnc, WQu_b);
    persist_kernel<<<NBLK, NTH, SMEM_BYTES>>>(quesEnc, passEnc,
                                              WPu_w, WPu_b, WPv_w, WPv_b,
                                              Wg_b, Vt,
                                              Whh_f, bih_f, bhh_f,
                                              Whh_r, bih_r, bhh_r,
                                              h0f, h0r, out);
}

// round 16
// speedup vs baseline: 1.5702x; 1.5702x over previous
#include <cuda_runtime.h>
#include <cuda_fp16.h>

typedef unsigned long long ull;

// Problem constants
constexpr int H   = 75;
constexpr int H3  = 225;
constexpr int H4  = 300;
constexpr int D2  = 150;
constexpr int NB  = 256;
constexpr int LQ  = 64;
constexpr int LP  = 500;

constexpr int G    = 4;
constexpr int NTH  = 512;             // 512 thr x ~127 regs = regfile optimum
constexpr int NBLK = (2 * NB) / G;    // 128 blocks

constexpr int KB8 = 38;               // Wih fp16 k-blocks (300->304)
constexpr int KBG = 19;               // Wg half / WPu k-blocks (150->152)
constexpr int KBH = 10;               // Whh/WPv k-blocks (75->80)
constexpr int QPS = 76;

// Shared-memory layout (float-slot offsets)
constexpr int HP   = 76;
constexpr int CCS  = 304;             // [p 0..149 | 00 | c 152..301 | 00]
constexpr int GIS  = 227;

constexpr int OFF_QPH  = 0;                      // [G][LQ][76] halves  = 9728 slots
constexpr int OFF_WHH  = 9728;                   // [10][225][8] halves = 9000
constexpr int OFF_WPV  = OFF_WHH + 9000;         // [10][75][8]         = 3000
constexpr int OFF_WPU  = OFF_WPV + 3000;         // [19][75][8]         = 5700
constexpr int OFF_WGC  = OFF_WPU + 5700;         // [19][300][8]        = 22800
constexpr int OFF_H    = OFF_WGC + 22800;        // [G][76]
constexpr int OFF_V    = OFF_H + G * HP;
constexpr int OFF_E    = OFF_V + G * HP;
constexpr int OFF_S    = OFF_E + G * HP;         // [G][64]
constexpr int OFF_PART = OFF_S + G * LQ;         // [2][G][64]
constexpr int OFF_CC   = OFF_PART + 2 * G * LQ;  // [G][304]
constexpr int OFF_X    = OFF_CC + G * CCS;       // [G][304]
constexpr int OFF_GI   = OFF_X + G * CCS;        // [G][227]
constexpr int OFF_GH   = OFF_GI + G * GIS;       // [G][227]
constexpr int SMEM_FLOATS = OFF_GH + G * GIS;    // 56188 slots
constexpr int SMEM_BYTES  = SMEM_FLOATS * 4;     // 224752 B

static_assert((OFF_WHH * 4) % 16 == 0 && (OFF_WPV * 4) % 16 == 0, "align");
static_assert((OFF_WPU * 4) % 16 == 0 && (OFF_WGC * 4) % 16 == 0, "align");
static_assert((OFF_H * 4) % 16 == 0 && (OFF_CC * 4) % 16 == 0, "align");
static_assert((OFF_X * 4) % 16 == 0, "align");
static_assert(SMEM_BYTES <= 232448, "smem over limit");

// Device scratch
__device__ __half g_QprojH[LQ * NB * H];
__device__ float  g_WQuT[D2 * H];
__device__ __align__(16) __half g_WgP[KBG * H4 * 8];        // Wg p-half fp16 [kb][j][8]
__device__ __align__(16) __half g_Wih4h[2][KB8 * H3 * 8];   // Wih fp16 per dir

// ---------- math helpers ----------
__device__ __forceinline__ float tanha(float x) {
    float r; asm("tanh.approx.f32 %0, %1;" : "=f"(r) : "f"(x)); return r;
}
__device__ __forceinline__ float siga(float x) {
    return fmaf(tanha(0.5f * x), 0.5f, 0.5f);
}
__device__ __forceinline__ ull pack2(float x, float y) {
    ull r; asm("mov.b64 %0, {%1, %2};" : "=l"(r) : "f"(x), "f"(y)); return r;
}
__device__ __forceinline__ void fma2(ull& d, ull a, ull b) {
    asm("fma.rn.f32x2 %0, %1, %2, %0;" : "+l"(d) : "l"(a), "l"(b));
}
__device__ __forceinline__ float hsum2(ull a) {
    float x, y; asm("mov.b64 {%0, %1}, %2;" : "=f"(x), "=f"(y) : "l"(a));
    return x + y;
}
__device__ __forceinline__ ull h2f2(unsigned v) {
    float2 f = __half22float2(*reinterpret_cast<const __half2*>(&v));
    return pack2(f.x, f.y);
}

#define LD2(p, idx) (*reinterpret_cast<const ulonglong2*>((p) + (idx)))

// ---------- prep: WQuT + Wg p-half + Wih fp16 packs ----------
__global__ void prep_kernel(const float* __restrict__ WQu,
                            const float* __restrict__ Wg,
                            const float* __restrict__ Wf,
                            const float* __restrict__ Wr) {
    int o = blockIdx.x * blockDim.x + threadIdx.x;
    if (o < D2 * H) {
        int k = o / H, j = o - k * H;
        g_WQuT[o] = WQu[j * D2 + k];
    } else if (o < D2 * H + KBG * H4 * 8) {            // Wg p-half (k 0..149)
        int o2 = o - D2 * H;
        int kb = o2 / 2400, r = o2 % 2400, j = r >> 3, c = r & 7;
        int k = kb * 8 + c;
        g_WgP[o2] = __float2half(k < D2 ? Wg[j * H4 + k] : 0.0f);
    } else if (o < D2 * H + KBG * H4 * 8 + 2 * KB8 * H3 * 8) {
        int o2 = o - D2 * H - KBG * H4 * 8;
        int d = o2 / (KB8 * H3 * 8);
        int o3 = o2 - d * (KB8 * H3 * 8);
        int kb = o3 / 1800, r = o3 % 1800, j = r >> 3, c = r & 7;
        int k = kb * 8 + c;
        const float* W = d ? Wr : Wf;
        g_Wih4h[d][o3] = __float2half(k < H4 ? W[j * H4 + k] : 0.0f);
    }
}
constexpr int PREP_N = D2 * H + KBG * H4 * 8 + 2 * KB8 * H3 * 8;

// ---------- Qproj ----------
__global__ void qproj_kernel(const float* __restrict__ X,
                             const float* __restrict__ bias) {
    int o = blockIdx.x * blockDim.x + threadIdx.x;
    if (o >= LQ * NB * H) return;
    int m = o / H;
    int j = o - m * H;
    const float* xr = X + (size_t)m * D2;
    float acc = bias[j];
#pragma unroll 15
    for (int k = 0; k < D2; k++) acc = fmaf(xr[k], g_WQuT[k * H + j], acc);
    g_QprojH[o] = __float2half(acc);
}

// ---------- persistent kernel ----------
__global__ __launch_bounds__(NTH, 1)
void persist_kernel(const float* __restrict__ quesEnc,
                    const float* __restrict__ passEnc,
                    const float* __restrict__ WPu_w, const float* __restrict__ WPu_b,
                    const float* __restrict__ WPv_w, const float* __restrict__ WPv_b,
                    const float* __restrict__ Wg_w,  const float* __restrict__ Wg_b,
                    const float* __restrict__ Vt,
                    const float* __restrict__ Whh_f,
                    const float* __restrict__ bih_f, const float* __restrict__ bhh_f,
                    const float* __restrict__ Whh_r,
                    const float* __restrict__ bih_r, const float* __restrict__ bhh_r,
                    const float* __restrict__ h0f,   const float* __restrict__ h0r,
                    float* __restrict__ out) {
    extern __shared__ float sm[];
    __half* qph  = reinterpret_cast<__half*>(sm + OFF_QPH);
    __half* whhH = reinterpret_cast<__half*>(sm + OFF_WHH);
    __half* wpvH = reinterpret_cast<__half*>(sm + OFF_WPV);
    __half* wpuH = reinterpret_cast<__half*>(sm + OFF_WPU);
    __half* wgcH = reinterpret_cast<__half*>(sm + OFF_WGC);
    const int tid   = threadIdx.x;
    const int item0 = blockIdx.x * G;
    const int dir   = item0 >> 8;

    // ---- one-time smem fills ----
    {
        const float* Whh = dir ? Whh_r : Whh_f;
        for (int idx = tid; idx < KBH * H3 * 8; idx += NTH) {     // WhhT fp16
            int kb = idx / 1800, r = idx % 1800, rr = r >> 3, c = r & 7;
            int k = kb * 8 + c;
            whhH[idx] = __float2half(k < H ? Whh[rr * H + k] : 0.0f);
        }
        for (int idx = tid; idx < KBH * H * 8; idx += NTH) {      // WPvT fp16
            int kb = idx / 600, r = idx % 600, j = r >> 3, c = r & 7;
            int k = kb * 8 + c;
            wpvH[idx] = __float2half(k < H ? WPv_w[j * H + k] : 0.0f);
        }
        for (int idx = tid; idx < KBG * H * 8; idx += NTH) {      // WPuT fp16
            int kb = idx / 600, r = idx % 600, j = r >> 3, c = r & 7;
            int k = kb * 8 + c;
            wpuH[idx] = __float2half(k < D2 ? WPu_w[j * D2 + k] : 0.0f);
        }
        for (int idx = tid; idx < KBG * H4 * 8; idx += NTH) {     // Wg c-half pinned
            int kb = idx / 2400, r = idx % 2400, j = r >> 3, c = r & 7;
            int k = D2 + kb * 8 + c;
            wgcH[idx] = __float2half(k < H4 ? Wg_w[j * H4 + k] : 0.0f);
        }
        const float* h0 = dir ? h0r : h0f;
        for (int idx = tid; idx < G * HP; idx += NTH) {
            int i = idx / HP, j = idx % HP;
            int b = (item0 + i) & 255;
            sm[OFF_H + idx] = (j < H) ? h0[b * H + j] : 0.0f;
            sm[OFF_V + idx] = (j < H) ? Vt[b * H + j] : 0.0f;
            sm[OFF_E + idx] = 0.0f;
        }
        for (int idx = tid; idx < 2 * G * CCS; idx += NTH)        // zero CC + X (pads!)
            sm[OFF_CC + idx] = 0.0f;
        for (int idx = tid; idx < G * LQ * QPS; idx += NTH) {     // Qproj fp16 slice
            int i = idx / (LQ * QPS);
            int r = idx - i * (LQ * QPS);
            int q = r / QPS, j = r - q * QPS;
            int b = (item0 + i) & 255;
            qph[idx] = (j < H) ? g_QprojH[((size_t)q * NB + b) * H + j]
                               : __float2half(0.0f);
        }
        int te0 = dir ? (LP - 1) : 0;
        for (int idx = tid; idx < G * D2; idx += NTH) {           // p(0)
            int i = idx / D2, d = idx - i * D2;
            int b = (item0 + i) & 255;
            sm[OFF_CC + i * CCS + d] = passEnc[((size_t)te0 * NB + b) * D2 + d];
        }
    }

    // ---- hoisted per-thread constants (R10 thread mapping) ----
    const int i1 = tid / H, j1 = tid % H;                 // p1-e / p7
    const bool p1_act = (tid < G * H);
    const float b_ph1 = p1_act ? (WPu_b[j1] + WPv_b[j1]) : 0.0f;

    const int half = tid & 1, pair = tid >> 1;            // p2: 2 threads / (i,q)
    const int i2 = pair >> 6, q2 = pair & 63;
    const __half2* qp2 = reinterpret_cast<const __half2*>(qph + i2 * (LQ * QPS) + q2 * QPS)
                         + (half ? 19 : 0);
    const float2* ee2 = reinterpret_cast<const float2*>(sm + OFF_E + i2 * HP) + (half ? 19 : 0);
    const float2* vv2 = reinterpret_cast<const float2*>(sm + OFF_V + i2 * HP) + (half ? 19 : 0);

    const float b_g  = (tid < H4) ? Wg_b[tid] : 0.0f;     // p5 (tid<300)

    const int j6 = tid >> 1, kh = tid & 1;                // p6 pair-split
    const bool p6_act = (tid < 2 * H3);
    const float b_ih = p6_act ? (dir ? bih_r : bih_f)[j6] : 0.0f;
    const unsigned shmask = (tid >= 448) ? 0x3u : 0xFFFFFFFFu;
    const float* bhh_d = dir ? bhh_r : bhh_f;

    const uint4* wgp_g  = reinterpret_cast<const uint4*>(g_WgP);
    const uint4* wi_all = reinterpret_cast<const uint4*>(g_Wih4h[dir]);
    const uint4* whh_u4 = reinterpret_cast<const uint4*>(whhH);
    const uint4* wpv_u4 = reinterpret_cast<const uint4*>(wpvH);
    const uint4* wpu_u4 = reinterpret_cast<const uint4*>(wpuH);
    const uint4* wgc_u4 = reinterpret_cast<const uint4*>(wgcH);

    const ull* x0c = reinterpret_cast<const ull*>(sm + OFF_CC);
    const ull* x1c = reinterpret_cast<const ull*>(sm + OFF_CC + CCS);
    const ull* x2c = reinterpret_cast<const ull*>(sm + OFF_CC + 2 * CCS);
    const ull* x3c = reinterpret_cast<const ull*>(sm + OFF_CC + 3 * CCS);
    const ull* x0x = reinterpret_cast<const ull*>(sm + OFF_X);
    const ull* x1x = reinterpret_cast<const ull*>(sm + OFF_X + CCS);
    const ull* x2x = reinterpret_cast<const ull*>(sm + OFF_X + 2 * CCS);
    const ull* x3x = reinterpret_cast<const ull*>(sm + OFF_X + 3 * CCS);
    const ull* hh0 = reinterpret_cast<const ull*>(sm + OFF_H);
    const ull* hh1 = reinterpret_cast<const ull*>(sm + OFF_H + HP);
    const ull* hh2 = reinterpret_cast<const ull*>(sm + OFF_H + 2 * HP);
    const ull* hh3 = reinterpret_cast<const ull*>(sm + OFF_H + 3 * HP);

    __syncthreads();

    // ================= main 500-step loop =================
    for (int t = 0; t < LP; t++) {
        float pf0 = 0.0f, pf1 = 0.0f, pf2 = 0.0f;   // p(t+1) prefetch regs

        // ---- phase 1: e = WPu@p + WPv@h (fp16 smem)  ||  gh = Whh@h (fp16 smem) ----
        if (p1_act) {
            ull aA = pack2(b_ph1, 0.0f), aB = 0ull;
            const ull* pp = (i1 == 0) ? x0c : (i1 == 1) ? x1c : (i1 == 2) ? x2c : x3c;
            const ull* hh = (i1 == 0) ? hh0 : (i1 == 1) ? hh1 : (i1 == 2) ? hh2 : hh3;
#pragma unroll
            for (int kb = 0; kb < KBG; kb++) {              // WPu @ p (k 0..151, pads 0)
                uint4 w = wpu_u4[kb * H + j1];
                ull w0 = h2f2(w.x), w1 = h2f2(w.y), w2 = h2f2(w.z), w3 = h2f2(w.w);
                ulonglong2 pa = LD2(pp, 4 * kb), pb = LD2(pp, 4 * kb + 2);
                fma2(aA, w0, pa.x); fma2(aB, w1, pa.y);
                fma2(aA, w2, pb.x); fma2(aB, w3, pb.y);
            }
#pragma unroll
            for (int kb = 0; kb < KBH; kb++) {              // WPv @ h (k 0..79, pads 0)
                uint4 w = wpv_u4[kb * H + j1];
                ull w0 = h2f2(w.x), w1 = h2f2(w.y), w2 = h2f2(w.z), w3 = h2f2(w.w);
                ulonglong2 pa = LD2(hh, 4 * kb), pb = LD2(hh, 4 * kb + 2);
                fma2(aA, w0, pa.x); fma2(aB, w1, pa.y);
                fma2(aA, w2, pb.x); fma2(aB, w3, pb.y);
            }
            sm[OFF_E + i1 * HP + j1] = hsum2(aA) + hsum2(aB);
        } else {
            for (int rr = tid - 300; rr < H3; rr += 212) {
                ull a0A = 0, a0B = 0, a1A = 0, a1B = 0;
                ull a2A = 0, a2B = 0, a3A = 0, a3B = 0;
#pragma unroll
                for (int kb = 0; kb < KBH; kb++) {
                    uint4 w = whh_u4[kb * H3 + rr];
                    ull w0 = h2f2(w.x), w1 = h2f2(w.y), w2 = h2f2(w.z), w3 = h2f2(w.w);
                    ulonglong2 pa, pb;
                    pa = LD2(hh0, 4 * kb); pb = LD2(hh0, 4 * kb + 2);
                    fma2(a0A, w0, pa.x); fma2(a0B, w1, pa.y); fma2(a0A, w2, pb.x); fma2(a0B, w3, pb.y);
                    pa = LD2(hh1, 4 * kb); pb = LD2(hh1, 4 * kb + 2);
                    fma2(a1A, w0, pa.x); fma2(a1B, w1, pa.y); fma2(a1A, w2, pb.x); fma2(a1B, w3, pb.y);
                    pa = LD2(hh2, 4 * kb); pb = LD2(hh2, 4 * kb + 2);
                    fma2(a2A, w0, pa.x); fma2(a2B, w1, pa.y); fma2(a2A, w2, pb.x); fma2(a2B, w3, pb.y);
                    pa = LD2(hh3, 4 * kb); pb = LD2(hh3, 4 * kb + 2);
                    fma2(a3A, w0, pa.x); fma2(a3B, w1, pa.y); fma2(a3A, w2, pb.x); fma2(a3B, w3, pb.y);
                }
                float bb = bhh_d[rr];
                sm[OFF_GH + 0 * GIS + rr] = hsum2(a0A) + hsum2(a0B) + bb;
                sm[OFF_GH + 1 * GIS + rr] = hsum2(a1A) + hsum2(a1B) + bb;
                sm[OFF_GH + 2 * GIS + rr] = hsum2(a2A) + hsum2(a2B) + bb;
                sm[OFF_GH + 3 * GIS + rr] = hsum2(a3A) + hsum2(a3B) + bb;
            }
        }
        __syncthreads();

        // ---- phase 2: attention scores (fixed 19x2) ----
        {
            float acc = 0.0f;
#pragma unroll
            for (int u = 0; u < 19; u++) {
                float2 qp = __half22float2(qp2[u]);
                float2 e = ee2[u], v = vv2[u];
                acc = fmaf(tanha(qp.x + e.x), v.x, acc);
                acc = fmaf(tanha(qp.y + e.y), v.y, acc);
            }
            sm[OFF_PART + half * (G * LQ) + i2 * LQ + q2] = acc;
        }
        __syncthreads();

        // ---- phase 3: softmax ----
        {
            int wid = tid >> 5, lane = tid & 31;
            if (wid < G) {
                float v0 = sm[OFF_PART + wid * LQ + lane]      + sm[OFF_PART + G * LQ + wid * LQ + lane];
                float v1 = sm[OFF_PART + wid * LQ + lane + 32] + sm[OFF_PART + G * LQ + wid * LQ + lane + 32];
                float m = fmaxf(v0, v1);
#pragma unroll
                for (int o = 16; o > 0; o >>= 1) m = fmaxf(m, __shfl_xor_sync(0xffffffffu, m, o));
                float e0 = __expf(v0 - m), e1 = __expf(v1 - m);
                float s = e0 + e1;
#pragma unroll
                for (int o = 16; o > 0; o >>= 1) s += __shfl_xor_sync(0xffffffffu, s, o);
                float inv = __fdividef(1.0f, s);
                sm[OFF_S + wid * LQ + lane]      = e0 * inv;
                sm[OFF_S + wid * LQ + lane + 32] = e1 * inv;
            }
        }
        __syncthreads();

        // ---- phase 4: context c -> cc[152..301] (float2, 300 threads) ----
        if (tid < G * 75) {
            int i = tid / 75, d2 = tid % 75;
            int b = (item0 + i) & 255;
            const float2* qe2 = reinterpret_cast<const float2*>(quesEnc + (size_t)b * D2) + d2;
            const float4* a4 = reinterpret_cast<const float4*>(sm + OFF_S + i * LQ);
            float ax = 0.0f, ay = 0.0f;
#pragma unroll
            for (int q4 = 0; q4 < 16; q4++) {
                float4 av = a4[q4];
                float2 v0 = qe2[(4 * q4 + 0) * (NB * 75)];
                float2 v1 = qe2[(4 * q4 + 1) * (NB * 75)];
                float2 v2 = qe2[(4 * q4 + 2) * (NB * 75)];
                float2 v3 = qe2[(4 * q4 + 3) * (NB * 75)];
                ax = fmaf(av.x, v0.x, ax); ay = fmaf(av.x, v0.y, ay);
                ax = fmaf(av.y, v1.x, ax); ay = fmaf(av.y, v1.y, ay);
                ax = fmaf(av.z, v2.x, ax); ay = fmaf(av.z, v2.y, ay);
                ax = fmaf(av.w, v3.x, ax); ay = fmaf(av.w, v3.y, ay);
            }
            reinterpret_cast<float2*>(sm + OFF_CC + i * CCS)[76 + d2] = make_float2(ax, ay);
        }
        __syncthreads();

        // ---- phase 5: x = siga(WgP@p [global] + Wgc@c [smem] + b)*cc || prefetch ----
        if (tid < H4) {
            int j = tid;
            ull a0A = 0, a0B = 0, a1A = 0, a1B = 0;
            ull a2A = 0, a2B = 0, a3A = 0, a3B = 0;
#pragma unroll
            for (int kb = 0; kb < KBG; kb++) {              // p-half: global fp16 stream
                uint4 w = wgp_g[kb * H4 + j];
                ull w0 = h2f2(w.x), w1 = h2f2(w.y), w2 = h2f2(w.z), w3 = h2f2(w.w);
                ulonglong2 pa, pb;
                pa = LD2(x0c, 4 * kb); pb = LD2(x0c, 4 * kb + 2);
                fma2(a0A, w0, pa.x); fma2(a0B, w1, pa.y); fma2(a0A, w2, pb.x); fma2(a0B, w3, pb.y);
                pa = LD2(x1c, 4 * kb); pb = LD2(x1c, 4 * kb + 2);
                fma2(a1A, w0, pa.x); fma2(a1B, w1, pa.y); fma2(a1A, w2, pb.x); fma2(a1B, w3, pb.y);
                pa = LD2(x2c, 4 * kb); pb = LD2(x2c, 4 * kb + 2);
                fma2(a2A, w0, pa.x); fma2(a2B, w1, pa.y); fma2(a2A, w2, pb.x); fma2(a2B, w3, pb.y);
                pa = LD2(x3c, 4 * kb); pb = LD2(x3c, 4 * kb + 2);
                fma2(a3A, w0, pa.x); fma2(a3B, w1, pa.y); fma2(a3A, w2, pb.x); fma2(a3B, w3, pb.y);
            }
#pragma unroll
            for (int kb = 0; kb < KBG; kb++) {              // c-half: pinned smem
                uint4 w = wgc_u4[kb * H4 + j];
                ull w0 = h2f2(w.x), w1 = h2f2(w.y), w2 = h2f2(w.z), w3 = h2f2(w.w);
                ulonglong2 pa, pb;
                pa = LD2(x0c, 76 + 4 * kb); pb = LD2(x0c, 78 + 4 * kb);
                fma2(a0A, w0, pa.x); fma2(a0B, w1, pa.y); fma2(a0A, w2, pb.x); fma2(a0B, w3, pb.y);
                pa = LD2(x1c, 76 + 4 * kb); pb = LD2(x1c, 78 + 4 * kb);
                fma2(a1A, w0, pa.x); fma2(a1B, w1, pa.y); fma2(a1A, w2, pb.x); fma2(a1B, w3, pb.y);
                pa = LD2(x2c, 76 + 4 * kb); pb = LD2(x2c, 78 + 4 * kb);
                fma2(a2A, w0, pa.x); fma2(a2B, w1, pa.y); fma2(a2A, w2, pb.x); fma2(a2B, w3, pb.y);
                pa = LD2(x3c, 76 + 4 * kb); pb = LD2(x3c, 78 + 4 * kb);
                fma2(a3A, w0, pa.x); fma2(a3B, w1, pa.y); fma2(a3A, w2, pb.x); fma2(a3B, w3, pb.y);
            }
            int cs = (j < D2) ? j : j + 2;                  // cc slot for dim j
            sm[OFF_X + 0 * CCS + j] = siga(hsum2(a0A) + hsum2(a0B) + b_g) * sm[OFF_CC + 0 * CCS + cs];
            sm[OFF_X + 1 * CCS + j] = siga(hsum2(a1A) + hsum2(a1B) + b_g) * sm[OFF_CC + 1 * CCS + cs];
            sm[OFF_X + 2 * CCS + j] = siga(hsum2(a2A) + hsum2(a2B) + b_g) * sm[OFF_CC + 2 * CCS + cs];
            sm[OFF_X + 3 * CCS + j] = siga(hsum2(a3A) + hsum2(a3B) + b_g) * sm[OFF_CC + 3 * CCS + cs];
        } else if (tid >= 308 && tid < 508) {
            int u = tid - 308;
            int tn = (t + 1 < LP) ? t + 1 : t;
            int ten = dir ? (LP - 1 - tn) : tn;
#pragma unroll
            for (int c = 0; c < 3; c++) {
                int e = 3 * u + c;
                int i = e / D2, d = e - i * D2;
                int b = (item0 + i) & 255;
                float v = passEnc[((size_t)ten * NB + b) * D2 + d];
                if (c == 0) pf0 = v; else if (c == 1) pf1 = v; else pf2 = v;
            }
        }
        __syncthreads();

        // ---- phase 6: gi = Wih@x + bih (fp16 global stream, pair-split k) ----
        if (p6_act) {
            ull a0A = 0, a0B = 0, a1A = 0, a1B = 0;
            ull a2A = 0, a2B = 0, a3A = 0, a3B = 0;
            const int kb0 = kh * 19;
#pragma unroll 19
            for (int kk = 0; kk < 19; kk++) {
                int kb = kb0 + kk;
                uint4 w = wi_all[kb * H3 + j6];
                ull w0 = h2f2(w.x), w1 = h2f2(w.y), w2 = h2f2(w.z), w3 = h2f2(w.w);
                ulonglong2 pa, pb;
                pa = LD2(x0x, 4 * kb); pb = LD2(x0x, 4 * kb + 2);
                fma2(a0A, w0, pa.x); fma2(a0B, w1, pa.y); fma2(a0A, w2, pb.x); fma2(a0B, w3, pb.y);
                pa = LD2(x1x, 4 * kb); pb = LD2(x1x, 4 * kb + 2);
                fma2(a1A, w0, pa.x); fma2(a1B, w1, pa.y); fma2(a1A, w2, pb.x); fma2(a1B, w3, pb.y);
                pa = LD2(x2x, 4 * kb); pb = LD2(x2x, 4 * kb + 2);
                fma2(a2A, w0, pa.x); fma2(a2B, w1, pa.y); fma2(a2A, w2, pb.x); fma2(a2B, w3, pb.y);
                pa = LD2(x3x, 4 * kb); pb = LD2(x3x, 4 * kb + 2);
                fma2(a3A, w0, pa.x); fma2(a3B, w1, pa.y); fma2(a3A, w2, pb.x); fma2(a3B, w3, pb.y);
            }
            float g0 = hsum2(a0A) + hsum2(a0B);
            float g1 = hsum2(a1A) + hsum2(a1B);
            float g2 = hsum2(a2A) + hsum2(a2B);
            float g3 = hsum2(a3A) + hsum2(a3B);
            g0 += __shfl_xor_sync(shmask, g0, 1);
            g1 += __shfl_xor_sync(shmask, g1, 1);
            g2 += __shfl_xor_sync(shmask, g2, 1);
            g3 += __shfl_xor_sync(shmask, g3, 1);
            if (kh == 0) {
                sm[OFF_GI + 0 * GIS + j6] = g0 + b_ih;
                sm[OFF_GI + 1 * GIS + j6] = g1 + b_ih;
                sm[OFF_GI + 2 * GIS + j6] = g2 + b_ih;
                sm[OFF_GI + 3 * GIS + j6] = g3 + b_ih;
            }
        }
        __syncthreads();

        // ---- phase 7: GRU combine + out || store p(t+1) ----
        if (tid < G * H) {
            int i = i1, j = j1;
            float gr  = sm[OFF_GI + i * GIS + j]         + sm[OFF_GH + i * GIS + j];
            float gz  = sm[OFF_GI + i * GIS + H + j]     + sm[OFF_GH + i * GIS + H + j];
            float gin = sm[OFF_GI + i * GIS + 2 * H + j];
            float ghn = sm[OFF_GH + i * GIS + 2 * H + j];
            float r = siga(gr);
            float z = siga(gz);
            float n = tanha(fmaf(r, ghn, gin));
            float hn = (1.0f - z) * n + z * sm[OFF_H + i * HP + j];
            sm[OFF_H + i * HP + j] = hn;
            int b = (item0 + i) & 255;
            out[((size_t)t * NB + b) * D2 + dir * H + j] = hn;
        } else if (tid >= 308 && tid < 508) {
            int u = tid - 308;
#pragma unroll
            for (int c = 0; c < 3; c++) {
                int e = 3 * u + c;
                int i = e / D2, d = e - i * D2;
                float v = (c == 0) ? pf0 : (c == 1) ? pf1 : pf2;
                sm[OFF_CC + i * CCS + d] = v;
            }
        }
        __syncthreads();
    }
}

extern "C" void kernel_launch(void* const* d_in, const int* in_sizes, int n_in,
                              void* d_out, int out_size) {
    const float* quesEnc = (const float*)d_in[0];
    const float* passEnc = (const float*)d_in[1];
    const float* WQu_w   = (const float*)d_in[2];
    const float* WQu_b   = (const float*)d_in[3];
    const float* WPu_w   = (const float*)d_in[4];
    const float* WPu_b   = (const float*)d_in[5];
    const float* WPv_w   = (const float*)d_in[6];
    const float* WPv_b   = (const float*)d_in[7];
    const float* Wg_w    = (const float*)d_in[8];
    const float* Wg_b    = (const float*)d_in[9];
    const float* Vt      = (const float*)d_in[10];
    const float* Wih_f   = (const float*)d_in[11];
    const float* Whh_f   = (const float*)d_in[12];
    const float* bih_f   = (const float*)d_in[13];
    const float* bhh_f   = (const float*)d_in[14];
    const float* Wih_r   = (const float*)d_in[15];
    const float* Whh_r   = (const float*)d_in[16];
    const float* bih_r   = (const float*)d_in[17];
    const float* bhh_r   = (const float*)d_in[18];
    const float* h0f     = (const float*)d_in[19];
    const float* h0r     = (const float*)d_in[20];
    float* out = (float*)d_out;

    cudaFuncSetAttribute(persist_kernel,
                         cudaFuncAttributeMaxDynamicSharedMemorySize, SMEM_BYTES);

    prep_kernel<<<(PREP_N + 255) / 256, 256>>>(WQu_w, Wg_w, Wih_f, Wih_r);
    qproj_kernel<<<(LQ * NB * H + 255) / 256, 256>>>(quesEnc, WQu_b);
    persist_kernel<<<NBLK, NTH, SMEM_BYTES>>>(quesEnc, passEnc,
                                              WPu_w, WPu_b, WPv_w, WPv_b,
                                              Wg_w, Wg_b, Vt,
                                              Whh_f, bih_f, bhh_f,
                                              Whh_r, bih_r, bhh_r,
                                              h0f, h0r, out);
}